// round 3
// baseline (speedup 1.0000x reference)
#include <cuda_runtime.h>

#define BB 16
#define NN 1024
#define CC 768
#define HH 9
#define HD 64
#define M_TOK (BB * NN)        // 16384
#define QKV_N (3 * HH * HD)    // 1728
#define ATT_N (HH * HD)        // 576

// Scratch (device globals — no allocation allowed)
__device__ float g_q[BB * HH * NN * HD];     // [B,H,N,HD]
__device__ float g_k[BB * HH * NN * HD];
__device__ float g_v[BB * HH * NN * HD];
__device__ float g_att[M_TOK * ATT_N];       // [B,N,H*HD]

// ---------------------------------------------------------------------------
// GEMM: C[M,N] = A[M,K] @ B[N,K]^T (+bias). Both operands K-contiguous.
// BM=128, BN=64, BK=8, 256 threads, 8x4 per-thread tile.
// MODE 0: A = x, scatter result into g_q/g_k/g_v with qkv bias.
// MODE 1: A = g_att (internal), plain store to C with bias.
// All dims divide tile sizes exactly (M=16384, N in {1728,768}, K in {768,576}).
// ---------------------------------------------------------------------------
template <int MODE>
__global__ __launch_bounds__(256) void gemm_kernel(
    const float* __restrict__ A, const float* __restrict__ Bm,
    const float* __restrict__ bias, float* __restrict__ C,
    int M, int N, int K)
{
    __shared__ float As[8][128];
    __shared__ float Bs[8][64];

    const int tid = threadIdx.x;
    const int tx = tid & 15;          // 0..15 -> 4 cols each
    const int ty = tid >> 4;          // 0..15 -> 8 rows each
    const int bm = blockIdx.x * 128;
    const int bn = blockIdx.y * 64;

    const float* Abase = (MODE == 0) ? A : g_att;

    const int arow = tid >> 1;              // 0..127
    const int ak   = (tid & 1) << 2;        // 0 or 4
    const float* Ag = Abase + (size_t)(bm + arow) * K + ak;

    const int brow = tid >> 1;              // 0..63 (only tid<128 used)
    const int bk   = (tid & 1) << 2;
    const float* Bg = Bm + (size_t)(bn + brow) * K + bk;

    float acc[8][4];
#pragma unroll
    for (int i = 0; i < 8; i++)
#pragma unroll
        for (int j = 0; j < 4; j++) acc[i][j] = 0.0f;

    for (int k0 = 0; k0 < K; k0 += 8) {
        float4 av = *(const float4*)(Ag + k0);
        float4 bv;
        if (tid < 128) bv = *(const float4*)(Bg + k0);

        As[ak + 0][arow] = av.x;
        As[ak + 1][arow] = av.y;
        As[ak + 2][arow] = av.z;
        As[ak + 3][arow] = av.w;
        if (tid < 128) {
            Bs[bk + 0][brow] = bv.x;
            Bs[bk + 1][brow] = bv.y;
            Bs[bk + 2][brow] = bv.z;
            Bs[bk + 3][brow] = bv.w;
        }
        __syncthreads();

#pragma unroll
        for (int k = 0; k < 8; k++) {
            float a[8], b[4];
#pragma unroll
            for (int i = 0; i < 8; i++) a[i] = As[k][ty * 8 + i];
#pragma unroll
            for (int j = 0; j < 4; j++) b[j] = Bs[k][tx * 4 + j];
#pragma unroll
            for (int i = 0; i < 8; i++)
#pragma unroll
                for (int j = 0; j < 4; j++) acc[i][j] = fmaf(a[i], b[j], acc[i][j]);
        }
        __syncthreads();
    }

    // Epilogue
    const int n0 = bn + tx * 4;     // 4 contiguous cols, never crossing a 64-boundary
    const float b0 = bias[n0], b1 = bias[n0 + 1], b2 = bias[n0 + 2], b3 = bias[n0 + 3];

#pragma unroll
    for (int i = 0; i < 8; i++) {
        const int m = bm + ty * 8 + i;
        float4 r = make_float4(acc[i][0] + b0, acc[i][1] + b1,
                               acc[i][2] + b2, acc[i][3] + b3);
        if (MODE == 0) {
            const int which = n0 / 576;
            const int rem   = n0 - which * 576;
            const int h     = rem >> 6;
            const int d     = rem & 63;         // multiple of 4
            const int b_    = m >> 10;
            const int tok   = m & 1023;
            float* dst = (which == 0) ? g_q : (which == 1) ? g_k : g_v;
            *(float4*)&dst[(((size_t)(b_ * HH + h) << 10) + tok) * HD + d] = r;
        } else {
            *(float4*)&C[(size_t)m * N + n0] = r;
        }
    }
}

// ---------------------------------------------------------------------------
// Flash attention: one block = 64 queries of one (b,h); KV tiles of 32.
// 256 threads: tx(16) x ty(16). Phase1: S 64x32 (4x2/thread). Phase2: O 64x64
// (4x4/thread). Online softmax state per row, replicated across tx.
// Static smem: 16640 + 8320 + 8192 + 8448 = 41600 B < 48KB.
// ---------------------------------------------------------------------------
__global__ __launch_bounds__(256) void attn_kernel()
{
    __shared__ float Qs[64][65];
    __shared__ float Ks[32][65];
    __shared__ float Vs[32][64];
    __shared__ float Ps[64][33];

    const int tid = threadIdx.x;
    const int tx = tid & 15;
    const int ty = tid >> 4;
    const int bh = blockIdx.y;                 // 0..143
    const int q0 = blockIdx.x * 64;

    const float* Qg = g_q + ((size_t)bh * NN + q0) * HD;
    const float* Kg = g_k + (size_t)bh * NN * HD;
    const float* Vg = g_v + (size_t)bh * NN * HD;

    const float scale = 0.125f;                // 1/sqrt(64)

    // Load Q tile (scaled): 64x64 = 1024 float4
    for (int idx = tid; idx < 1024; idx += 256) {
        float4 v = ((const float4*)Qg)[idx];
        int r = idx >> 4, c = (idx & 15) << 2;
        Qs[r][c]     = v.x * scale;
        Qs[r][c + 1] = v.y * scale;
        Qs[r][c + 2] = v.z * scale;
        Qs[r][c + 3] = v.w * scale;
    }

    float m_i[4], l_i[4], o[4][4];
#pragma unroll
    for (int i = 0; i < 4; i++) {
        m_i[i] = -1e30f;
        l_i[i] = 0.0f;
#pragma unroll
        for (int j = 0; j < 4; j++) o[i][j] = 0.0f;
    }

    for (int kt = 0; kt < NN; kt += 32) {
        __syncthreads();   // prev phase2 done with Vs/Ps; Qs ready on 1st iter

        // Load K,V tiles: 32x64 = 512 float4 each
        const float4* Kt = (const float4*)(Kg + (size_t)kt * HD);
        const float4* Vt = (const float4*)(Vg + (size_t)kt * HD);
        for (int idx = tid; idx < 512; idx += 256) {
            int r = idx >> 4, c = (idx & 15) << 2;
            float4 kv = Kt[idx];
            Ks[r][c] = kv.x; Ks[r][c + 1] = kv.y; Ks[r][c + 2] = kv.z; Ks[r][c + 3] = kv.w;
            float4 vv = Vt[idx];
            *(float4*)&Vs[r][c] = vv;
        }
        __syncthreads();

        // Phase 1: S[64x32] = Qs @ Ks^T (already scaled)
        float s[4][2];
#pragma unroll
        for (int i = 0; i < 4; i++) { s[i][0] = 0.0f; s[i][1] = 0.0f; }
#pragma unroll 16
        for (int d = 0; d < 64; d++) {
            float q[4], kk[2];
#pragma unroll
            for (int i = 0; i < 4; i++) q[i] = Qs[ty * 4 + i][d];
#pragma unroll
            for (int j = 0; j < 2; j++) kk[j] = Ks[tx * 2 + j][d];
#pragma unroll
            for (int i = 0; i < 4; i++) {
                s[i][0] = fmaf(q[i], kk[0], s[i][0]);
                s[i][1] = fmaf(q[i], kk[1], s[i][1]);
            }
        }

        // Online softmax update per row (row split over 16 tx lanes)
#pragma unroll
        for (int i = 0; i < 4; i++) {
            float mt = fmaxf(s[i][0], s[i][1]);
#pragma unroll
            for (int off = 8; off > 0; off >>= 1)
                mt = fmaxf(mt, __shfl_xor_sync(0xffffffffu, mt, off, 16));
            float mnew = fmaxf(m_i[i], mt);
            float corr = __expf(m_i[i] - mnew);
            m_i[i] = mnew;
            float p0 = __expf(s[i][0] - mnew);
            float p1 = __expf(s[i][1] - mnew);
            Ps[ty * 4 + i][tx * 2]     = p0;
            Ps[ty * 4 + i][tx * 2 + 1] = p1;
            float rs = p0 + p1;
#pragma unroll
            for (int off = 8; off > 0; off >>= 1)
                rs += __shfl_xor_sync(0xffffffffu, rs, off, 16);
            l_i[i] = l_i[i] * corr + rs;
#pragma unroll
            for (int j = 0; j < 4; j++) o[i][j] *= corr;
        }
        __syncthreads();

        // Phase 2: O[64x64] += Ps[64x32] @ Vs[32x64]
#pragma unroll 8
        for (int k = 0; k < 32; k++) {
            float4 vv = *(const float4*)&Vs[k][tx << 2];
#pragma unroll
            for (int i = 0; i < 4; i++) {
                float p = Ps[ty * 4 + i][k];
                o[i][0] = fmaf(p, vv.x, o[i][0]);
                o[i][1] = fmaf(p, vv.y, o[i][1]);
                o[i][2] = fmaf(p, vv.z, o[i][2]);
                o[i][3] = fmaf(p, vv.w, o[i][3]);
            }
        }
    }

    // Normalize and write to g_att in [B, N, H*HD] layout
    const int b_ = bh / HH;
    const int h  = bh - b_ * HH;
#pragma unroll
    for (int i = 0; i < 4; i++) {
        float inv = 1.0f / l_i[i];
        int tok = q0 + ty * 4 + i;
        float4 r = make_float4(o[i][0] * inv, o[i][1] * inv,
                               o[i][2] * inv, o[i][3] * inv);
        *(float4*)&g_att[((size_t)(b_ * NN + tok)) * ATT_N + h * HD + (tx << 2)] = r;
    }
}

// ---------------------------------------------------------------------------
extern "C" void kernel_launch(void* const* d_in, const int* in_sizes, int n_in,
                              void* d_out, int out_size)
{
    const float* x      = (const float*)d_in[0];
    const float* qkv_w  = (const float*)d_in[1];
    const float* qkv_b  = (const float*)d_in[2];
    const float* proj_w = (const float*)d_in[3];
    const float* proj_b = (const float*)d_in[4];
    float* out = (float*)d_out;

    // 1) QKV projection + bias + scatter to [B,H,N,HD]
    dim3 g1(M_TOK / 128, QKV_N / 64);
    gemm_kernel<0><<<g1, 256>>>(x, qkv_w, qkv_b, nullptr, M_TOK, QKV_N, CC);

    // 2) Flash attention -> g_att [B,N,H*HD]
    dim3 g2(NN / 64, BB * HH);
    attn_kernel<<<g2, 256>>>();

    // 3) Output projection + bias
    dim3 g3(M_TOK / 128, CC / 64);
    gemm_kernel<1><<<g3, 256>>>(nullptr, proj_w, proj_b, out, M_TOK, CC, ATT_N);
}

// round 7
// speedup vs baseline: 2.7304x; 2.7304x over previous
#include <cuda_runtime.h>
#include <cstdint>

#define BB 16
#define NN 1024
#define CC 768
#define HH 9
#define HD 64
#define M_TOK (BB * NN)        // 16384
#define QKV_N (3 * HH * HD)    // 1728
#define ATT_N (HH * HD)        // 576

// Scratch (device globals — no allocation allowed)
__device__ float g_q[BB * HH * NN * HD];     // [B,H,N,HD]
__device__ float g_k[BB * HH * NN * HD];
__device__ float g_v[BB * HH * NN * HD];
__device__ float g_att[M_TOK * ATT_N];       // [B,N,H*HD]

// ---------------------------------------------------------------------------
// TF32 helpers
// ---------------------------------------------------------------------------
__device__ __forceinline__ uint32_t f2tf(float x) {
    uint32_t r;
    asm("cvt.rna.tf32.f32 %0, %1;" : "=r"(r) : "f"(x));
    return r;
}

// D(16x8,f32) += A(16x8,tf32,row) * B(8x8,tf32,col)
__device__ __forceinline__ void mma_tf32(float* d,
    uint32_t a0, uint32_t a1, uint32_t a2, uint32_t a3,
    uint32_t b0, uint32_t b1)
{
    asm volatile(
        "mma.sync.aligned.m16n8k8.row.col.f32.tf32.tf32.f32 "
        "{%0,%1,%2,%3}, {%4,%5,%6,%7}, {%8,%9}, {%0,%1,%2,%3};"
        : "+f"(d[0]), "+f"(d[1]), "+f"(d[2]), "+f"(d[3])
        : "r"(a0), "r"(a1), "r"(a2), "r"(a3), "r"(b0), "r"(b1));
}

// ---------------------------------------------------------------------------
// GEMM (tensor core): C[M,N] = A[M,K] @ B[N,K]^T + bias.
// Block 128x64, BK=32, 256 threads, 8 warps in 4(M)x2(N), warp tile 32x32.
// Fragment layouts (mma.m16n8k8.tf32, lane g = lane>>2, t = lane&3):
//   A: a0=(g,t) a1=(g+8,t) a2=(g,t+4) a3=(g+8,t+4)   [row=m, col=k]
//   B: b0=(t,g) b1=(t+4,g)                           [row=k, col=n]
//   C: c0=(g,2t) c1=(g,2t+1) c2=(g+8,2t) c3=(g+8,2t+1)
// smem stride 36 -> frag-load bank = 4g+t = lane (conflict-free).
// MODE 0: A = x, scatter into g_q/g_k/g_v (each 64-col block = one head chunk).
// MODE 1: A = g_att, plain store.
// ---------------------------------------------------------------------------
template <int MODE>
__global__ __launch_bounds__(256) void gemm_tc(
    const float* __restrict__ A, const float* __restrict__ Bw,
    const float* __restrict__ bias, float* __restrict__ C,
    int M, int N, int K)
{
    __shared__ uint32_t As[128][36];
    __shared__ uint32_t Bs[64][36];

    const int tid  = threadIdx.x;
    const int lane = tid & 31;
    const int warp = tid >> 5;
    const int wm = warp & 3;       // 0..3  (M groups of 32)
    const int wn = warp >> 2;      // 0..1  (N groups of 32)
    const int g = lane >> 2, t = lane & 3;
    const int bm = blockIdx.x * 128;
    const int bn = blockIdx.y * 64;

    const float* Ab = (MODE == 0) ? A : g_att;

    float acc[2][4][4];
#pragma unroll
    for (int mt = 0; mt < 2; mt++)
#pragma unroll
        for (int nt = 0; nt < 4; nt++)
#pragma unroll
            for (int i = 0; i < 4; i++) acc[mt][nt][i] = 0.0f;

    for (int k0 = 0; k0 < K; k0 += 32) {
        // A tile: 128x32 = 1024 float4
#pragma unroll
        for (int i = 0; i < 4; i++) {
            int idx = tid + 256 * i;
            int r = idx >> 3, c = (idx & 7) << 2;
            float4 v = *(const float4*)(Ab + (size_t)(bm + r) * K + k0 + c);
            As[r][c]     = f2tf(v.x);
            As[r][c + 1] = f2tf(v.y);
            As[r][c + 2] = f2tf(v.z);
            As[r][c + 3] = f2tf(v.w);
        }
        // B tile: 64x32 = 512 float4
#pragma unroll
        for (int i = 0; i < 2; i++) {
            int idx = tid + 256 * i;
            int r = idx >> 3, c = (idx & 7) << 2;
            float4 v = *(const float4*)(Bw + (size_t)(bn + r) * K + k0 + c);
            Bs[r][c]     = f2tf(v.x);
            Bs[r][c + 1] = f2tf(v.y);
            Bs[r][c + 2] = f2tf(v.z);
            Bs[r][c + 3] = f2tf(v.w);
        }
        __syncthreads();

#pragma unroll
        for (int ks = 0; ks < 4; ks++) {
            const int kk = ks * 8;
            uint32_t a[2][4], b[4][2];
#pragma unroll
            for (int mt = 0; mt < 2; mt++) {
                int r = wm * 32 + mt * 16 + g;
                a[mt][0] = As[r][kk + t];
                a[mt][1] = As[r + 8][kk + t];
                a[mt][2] = As[r][kk + t + 4];
                a[mt][3] = As[r + 8][kk + t + 4];
            }
#pragma unroll
            for (int nt = 0; nt < 4; nt++) {
                int n = wn * 32 + nt * 8 + g;
                b[nt][0] = Bs[n][kk + t];
                b[nt][1] = Bs[n][kk + t + 4];
            }
#pragma unroll
            for (int mt = 0; mt < 2; mt++)
#pragma unroll
                for (int nt = 0; nt < 4; nt++)
                    mma_tf32(acc[mt][nt], a[mt][0], a[mt][1], a[mt][2], a[mt][3],
                             b[nt][0], b[nt][1]);
        }
        __syncthreads();
    }

    // Epilogue
    if (MODE == 0) {
        // Block's 64 cols lie in exactly one of q/k/v and one head
        // (576 = 9*64, bn multiple of 64).
        const int which = bn / 576;
        const int h     = (bn % 576) >> 6;
        float* dst = (which == 0) ? g_q : (which == 1) ? g_k : g_v;
#pragma unroll
        for (int mt = 0; mt < 2; mt++) {
#pragma unroll
            for (int half = 0; half < 2; half++) {
                int m = bm + wm * 32 + mt * 16 + g + half * 8;
                int b_ = m >> 10, tok = m & 1023;
                float* rowp = dst + (((size_t)(b_ * HH + h) << 10) + tok) * HD;
#pragma unroll
                for (int nt = 0; nt < 4; nt++) {
                    int d = wn * 32 + nt * 8 + t * 2;
                    int col = bn + d;
                    float2 r = make_float2(acc[mt][nt][half * 2]     + bias[col],
                                           acc[mt][nt][half * 2 + 1] + bias[col + 1]);
                    *(float2*)(rowp + d) = r;
                }
            }
        }
    } else {
#pragma unroll
        for (int mt = 0; mt < 2; mt++) {
#pragma unroll
            for (int half = 0; half < 2; half++) {
                int m = bm + wm * 32 + mt * 16 + g + half * 8;
#pragma unroll
                for (int nt = 0; nt < 4; nt++) {
                    int col = bn + wn * 32 + nt * 8 + t * 2;
                    float2 r = make_float2(acc[mt][nt][half * 2]     + bias[col],
                                           acc[mt][nt][half * 2 + 1] + bias[col + 1]);
                    *(float2*)&C[(size_t)m * N + col] = r;
                }
            }
        }
    }
}

// ---------------------------------------------------------------------------
// Flash attention (tensor core): block = 128 queries of one (b,h), KV tiles 64.
// 8 warps; each warp owns 16 query rows end-to-end (no cross-warp softmax).
// S = Q@K^T via mma (Q pre-scaled), fp32 online softmax in registers,
// P -> smem (tf32) -> PV mma. V stored transposed [d][key] with XOR swizzle.
// Dynamic smem: Qs 128x68 + Ks 64x68 + Vs 64x64 + Ps 128x68 = 103424 B.
// ---------------------------------------------------------------------------
#define ATTN_SMEM_BYTES (128*68*4 + 64*68*4 + 64*64*4 + 128*68*4)

__device__ __forceinline__ int vsw(int d, int key) {  // Vs swizzled flat index
    return d * 64 + (key ^ ((d & 7) << 2));
}

__global__ __launch_bounds__(256) void attn_tc()
{
    extern __shared__ char sraw[];
    uint32_t (*Qs)[68] = reinterpret_cast<uint32_t(*)[68]>(sraw);
    uint32_t (*Ks)[68] = reinterpret_cast<uint32_t(*)[68]>(sraw + 128 * 68 * 4);
    uint32_t* VsF      = reinterpret_cast<uint32_t*>(sraw + (128 + 64) * 68 * 4);
    uint32_t (*Ps)[68] = reinterpret_cast<uint32_t(*)[68]>(sraw + (128 + 64) * 68 * 4 + 64 * 64 * 4);

    const int tid  = threadIdx.x;
    const int lane = tid & 31;
    const int warp = tid >> 5;
    const int g = lane >> 2, t = lane & 3;
    const int bh = blockIdx.y;                 // 0..143
    const int q0 = blockIdx.x * 128;
    const int qr = warp * 16;                  // warp's query rows within tile

    const float* Qg = g_q + ((size_t)bh * NN + q0) * HD;
    const float* Kg = g_k + (size_t)bh * NN * HD;
    const float* Vg = g_v + (size_t)bh * NN * HD;

    // Load Q tile (pre-scaled by 1/sqrt(64)): 128x64 = 2048 float4
#pragma unroll
    for (int i = 0; i < 8; i++) {
        int idx = tid + 256 * i;
        int r = idx >> 4, c = (idx & 15) << 2;
        float4 v = ((const float4*)Qg)[idx];
        Qs[r][c]     = f2tf(v.x * 0.125f);
        Qs[r][c + 1] = f2tf(v.y * 0.125f);
        Qs[r][c + 2] = f2tf(v.z * 0.125f);
        Qs[r][c + 3] = f2tf(v.w * 0.125f);
    }

    float m_i[2] = {-1e30f, -1e30f};
    float l_i[2] = {0.0f, 0.0f};
    float o[8][4];
#pragma unroll
    for (int nt = 0; nt < 8; nt++)
#pragma unroll
        for (int i = 0; i < 4; i++) o[nt][i] = 0.0f;

    for (int kt = 0; kt < NN; kt += 64) {
        __syncthreads();   // prev iter's MMAs done with Ks/Vs

        // K tile 64x64 (row-coalesced)
#pragma unroll
        for (int i = 0; i < 4; i++) {
            int idx = tid + 256 * i;
            int r = idx >> 4, c = (idx & 15) << 2;
            float4 kv = *(const float4*)(Kg + (size_t)(kt + r) * HD + c);
            Ks[r][c]     = f2tf(kv.x);
            Ks[r][c + 1] = f2tf(kv.y);
            Ks[r][c + 2] = f2tf(kv.z);
            Ks[r][c + 3] = f2tf(kv.w);
        }
        // V tile transposed into Vs[d][key] (lane -> distinct key: conflict-free)
#pragma unroll
        for (int i = 0; i < 4; i++) {
            int idx = tid + 256 * i;
            int r = idx & 63;            // key
            int c = (idx >> 6) << 2;     // d base
            float4 vv = *(const float4*)(Vg + (size_t)(kt + r) * HD + c);
            VsF[vsw(c,     r)] = f2tf(vv.x);
            VsF[vsw(c + 1, r)] = f2tf(vv.y);
            VsF[vsw(c + 2, r)] = f2tf(vv.z);
            VsF[vsw(c + 3, r)] = f2tf(vv.w);
        }
        __syncthreads();

        // S[16x64] = Q(warp rows) @ K^T
        float s[8][4];
#pragma unroll
        for (int nt = 0; nt < 8; nt++)
#pragma unroll
            for (int i = 0; i < 4; i++) s[nt][i] = 0.0f;

#pragma unroll
        for (int ks = 0; ks < 8; ks++) {
            const int kk = ks * 8;
            const int r = qr + g;
            uint32_t a0 = Qs[r][kk + t],     a1 = Qs[r + 8][kk + t];
            uint32_t a2 = Qs[r][kk + t + 4], a3 = Qs[r + 8][kk + t + 4];
#pragma unroll
            for (int nt = 0; nt < 8; nt++) {
                int n = nt * 8 + g;
                mma_tf32(s[nt], a0, a1, a2, a3, Ks[n][kk + t], Ks[n][kk + t + 4]);
            }
        }

        // Online softmax: rows r0 = qr+g, r1 = qr+g+8 (4 lanes/row group)
        float mt0 = -1e30f, mt1 = -1e30f;
#pragma unroll
        for (int nt = 0; nt < 8; nt++) {
            mt0 = fmaxf(mt0, fmaxf(s[nt][0], s[nt][1]));
            mt1 = fmaxf(mt1, fmaxf(s[nt][2], s[nt][3]));
        }
        mt0 = fmaxf(mt0, __shfl_xor_sync(0xffffffffu, mt0, 1));
        mt0 = fmaxf(mt0, __shfl_xor_sync(0xffffffffu, mt0, 2));
        mt1 = fmaxf(mt1, __shfl_xor_sync(0xffffffffu, mt1, 1));
        mt1 = fmaxf(mt1, __shfl_xor_sync(0xffffffffu, mt1, 2));

        float mn0 = fmaxf(m_i[0], mt0), mn1 = fmaxf(m_i[1], mt1);
        float c0 = __expf(m_i[0] - mn0), c1 = __expf(m_i[1] - mn1);
        m_i[0] = mn0; m_i[1] = mn1;

        float rs0 = 0.0f, rs1 = 0.0f;
#pragma unroll
        for (int nt = 0; nt < 8; nt++) {
            float p00 = __expf(s[nt][0] - mn0);
            float p01 = __expf(s[nt][1] - mn0);
            float p10 = __expf(s[nt][2] - mn1);
            float p11 = __expf(s[nt][3] - mn1);
            rs0 += p00 + p01;
            rs1 += p10 + p11;
            int col = nt * 8 + t * 2;
            uint2 w0 = make_uint2(f2tf(p00), f2tf(p01));
            uint2 w1 = make_uint2(f2tf(p10), f2tf(p11));
            *(uint2*)&Ps[qr + g][col]     = w0;
            *(uint2*)&Ps[qr + g + 8][col] = w1;
        }
        rs0 += __shfl_xor_sync(0xffffffffu, rs0, 1);
        rs0 += __shfl_xor_sync(0xffffffffu, rs0, 2);
        rs1 += __shfl_xor_sync(0xffffffffu, rs1, 1);
        rs1 += __shfl_xor_sync(0xffffffffu, rs1, 2);
        l_i[0] = l_i[0] * c0 + rs0;
        l_i[1] = l_i[1] * c1 + rs1;
#pragma unroll
        for (int nt = 0; nt < 8; nt++) {
            o[nt][0] *= c0; o[nt][1] *= c0;
            o[nt][2] *= c1; o[nt][3] *= c1;
        }
        __syncwarp();   // Ps visible within warp (Ps rows are warp-private)

        // O[16x64] += P[16x64] @ V[64x64]
#pragma unroll
        for (int ks = 0; ks < 8; ks++) {
            const int kk = ks * 8;
            const int r = qr + g;
            uint32_t a0 = Ps[r][kk + t],     a1 = Ps[r + 8][kk + t];
            uint32_t a2 = Ps[r][kk + t + 4], a3 = Ps[r + 8][kk + t + 4];
#pragma unroll
            for (int nt = 0; nt < 8; nt++) {
                int n = nt * 8 + g;
                mma_tf32(o[nt], a0, a1, a2, a3,
                         VsF[vsw(n, kk + t)], VsF[vsw(n, kk + t + 4)]);
            }
        }
    }

    // Epilogue: normalize, write g_att [B,N,H*HD]
    const int b_ = bh / HH;
    const int h  = bh - b_ * HH;
    const float inv0 = 1.0f / l_i[0];
    const float inv1 = 1.0f / l_i[1];
    const int tok0 = q0 + qr + g;
    const int tok1 = tok0 + 8;
    float* p0 = g_att + (size_t)(b_ * NN + tok0) * ATT_N + h * HD;
    float* p1 = g_att + (size_t)(b_ * NN + tok1) * ATT_N + h * HD;
#pragma unroll
    for (int nt = 0; nt < 8; nt++) {
        int d = nt * 8 + t * 2;
        *(float2*)(p0 + d) = make_float2(o[nt][0] * inv0, o[nt][1] * inv0);
        *(float2*)(p1 + d) = make_float2(o[nt][2] * inv1, o[nt][3] * inv1);
    }
}

// ---------------------------------------------------------------------------
extern "C" void kernel_launch(void* const* d_in, const int* in_sizes, int n_in,
                              void* d_out, int out_size)
{
    const float* x      = (const float*)d_in[0];
    const float* qkv_w  = (const float*)d_in[1];
    const float* qkv_b  = (const float*)d_in[2];
    const float* proj_w = (const float*)d_in[3];
    const float* proj_b = (const float*)d_in[4];
    float* out = (float*)d_out;

    cudaFuncSetAttribute(attn_tc, cudaFuncAttributeMaxDynamicSharedMemorySize,
                         ATTN_SMEM_BYTES);

    // 1) QKV projection + bias + scatter to [B,H,N,HD]
    dim3 g1(M_TOK / 128, QKV_N / 64);
    gemm_tc<0><<<g1, 256>>>(x, qkv_w, qkv_b, nullptr, M_TOK, QKV_N, CC);

    // 2) Flash attention -> g_att [B,N,H*HD]
    dim3 g2(NN / 128, BB * HH);
    attn_tc<<<g2, 256, ATTN_SMEM_BYTES>>>();

    // 3) Output projection + bias
    dim3 g3(M_TOK / 128, CC / 64);
    gemm_tc<1><<<g3, 256>>>(nullptr, proj_w, proj_b, out, M_TOK, CC, ATT_N);
}